// round 3
// baseline (speedup 1.0000x reference)
#include <cuda_runtime.h>

// Problem constants
#define B_   4
#define L_   2048
#define D_   1024
#define H_   16
#define HD_  64
#define MTOT (B_ * L_)   // 8192

// Scratch (device globals; no allocation allowed)
__device__ float g_Q[B_ * L_ * D_];
__device__ float g_K[B_ * L_ * D_];
__device__ float g_V[B_ * L_ * D_];
__device__ float g_X[B_ * L_ * D_];

// ---------------------------------------------------------------------------
// GEMM: Y[M,N] = X[M,K] @ W[N,K]^T + bias[N]      (M=8192, N=K=1024 fixed)
// 128x128 block tile, BK=8, 8x8 per-thread micro-tile, 256 threads.
// ---------------------------------------------------------------------------
#define BM 128
#define BN 128
#define BKK 8
#define TM 8
#define TN 8

__global__ __launch_bounds__(256) void gemm_bias_kernel(
    const float* __restrict__ X, const float* __restrict__ W,
    const float* __restrict__ bias, float* __restrict__ Y)
{
    __shared__ float As[BKK][BM];
    __shared__ float Bs[BKK][BN];

    const int tid  = threadIdx.x;
    const int tCol = tid & 15;       // 0..15 -> N micro
    const int tRow = tid >> 4;       // 0..15 -> M micro

    const float* Xb = X + (size_t)blockIdx.y * BM * D_;
    const float* Wb = W + (size_t)blockIdx.x * BN * D_;

    const int ldRow = tid >> 1;        // 0..127
    const int ldK   = (tid & 1) * 4;   // 0 or 4

    float acc[TM][TN];
#pragma unroll
    for (int i = 0; i < TM; i++)
#pragma unroll
        for (int j = 0; j < TN; j++) acc[i][j] = 0.f;

    for (int k0 = 0; k0 < D_; k0 += BKK) {
        float4 xv = *reinterpret_cast<const float4*>(Xb + (size_t)ldRow * D_ + k0 + ldK);
        float4 wv = *reinterpret_cast<const float4*>(Wb + (size_t)ldRow * D_ + k0 + ldK);
        As[ldK + 0][ldRow] = xv.x; As[ldK + 1][ldRow] = xv.y;
        As[ldK + 2][ldRow] = xv.z; As[ldK + 3][ldRow] = xv.w;
        Bs[ldK + 0][ldRow] = wv.x; Bs[ldK + 1][ldRow] = wv.y;
        Bs[ldK + 2][ldRow] = wv.z; Bs[ldK + 3][ldRow] = wv.w;
        __syncthreads();

#pragma unroll
        for (int k = 0; k < BKK; k++) {
            float rm[TM], rn[TN];
            *reinterpret_cast<float4*>(rm)     = *reinterpret_cast<const float4*>(&As[k][tRow * TM]);
            *reinterpret_cast<float4*>(rm + 4) = *reinterpret_cast<const float4*>(&As[k][tRow * TM + 4]);
            *reinterpret_cast<float4*>(rn)     = *reinterpret_cast<const float4*>(&Bs[k][tCol * TN]);
            *reinterpret_cast<float4*>(rn + 4) = *reinterpret_cast<const float4*>(&Bs[k][tCol * TN + 4]);
#pragma unroll
            for (int i = 0; i < TM; i++)
#pragma unroll
                for (int j = 0; j < TN; j++)
                    acc[i][j] += rm[i] * rn[j];
        }
        __syncthreads();
    }

    const int n0 = blockIdx.x * BN + tCol * TN;
    float bv[TN];
    *reinterpret_cast<float4*>(bv)     = *reinterpret_cast<const float4*>(bias + n0);
    *reinterpret_cast<float4*>(bv + 4) = *reinterpret_cast<const float4*>(bias + n0 + 4);

#pragma unroll
    for (int i = 0; i < TM; i++) {
        float* yrow = Y + (size_t)(blockIdx.y * BM + tRow * TM + i) * D_ + n0;
        float4 o0, o1;
        o0.x = acc[i][0] + bv[0]; o0.y = acc[i][1] + bv[1];
        o0.z = acc[i][2] + bv[2]; o0.w = acc[i][3] + bv[3];
        o1.x = acc[i][4] + bv[4]; o1.y = acc[i][5] + bv[5];
        o1.z = acc[i][6] + bv[6]; o1.w = acc[i][7] + bv[7];
        *reinterpret_cast<float4*>(yrow)     = o0;
        *reinterpret_cast<float4*>(yrow + 4) = o1;
    }
}

// ---------------------------------------------------------------------------
// Flash attention (fp32, online softmax).
// One CTA: 64 Q rows of one (b,h). Loops over 64-row K/V tiles.
// Thread (ty,tx): ty=tid/16, tx=tid%16.
//   S/P element (r,c): r = ty+16i, c = tx+16j  (4x4 per thread)
//   O element (r,d):  r = ty+16i, d = tx+16j   (4x4 per thread)
// Row groups (fixed ty) are half-warps -> shfl width 16 reductions.
// Smem: Qs[64][65], KPs[64][65] (K tile, then reused for P), Vs[64][65].
// ---------------------------------------------------------------------------
#define BQ  64
#define BKV 64
#define PAD 65
#define FLASH_SMEM_BYTES (3 * BQ * PAD * 4)

__global__ __launch_bounds__(256) void flash_kernel(
    const float* __restrict__ Q, const float* __restrict__ K,
    const float* __restrict__ V, float* __restrict__ O)
{
    extern __shared__ float sm[];
    float* Qs  = sm;                 // BQ  * PAD
    float* KPs = sm + BQ * PAD;      // BKV * PAD
    float* Vs  = sm + 2 * BQ * PAD;  // BKV * PAD

    const int tid = threadIdx.x;
    const int tx  = tid & 15;
    const int ty  = tid >> 4;
    const int q0  = blockIdx.x * BQ;
    const int h   = blockIdx.y;
    const int b   = blockIdx.z;

    const float* Qbase = Q + (size_t)(b * L_ + q0) * D_ + h * HD_;
    const float* Kbase = K + (size_t)(b * L_) * D_ + h * HD_;
    const float* Vbase = V + (size_t)(b * L_) * D_ + h * HD_;

    // Load Q tile, pre-scaled by 1/sqrt(HD) = 0.125
    for (int e = tid; e < BQ * 16; e += 256) {
        int r  = e >> 4;
        int c4 = (e & 15) * 4;
        float4 v = *reinterpret_cast<const float4*>(Qbase + (size_t)r * D_ + c4);
        Qs[r * PAD + c4 + 0] = v.x * 0.125f;
        Qs[r * PAD + c4 + 1] = v.y * 0.125f;
        Qs[r * PAD + c4 + 2] = v.z * 0.125f;
        Qs[r * PAD + c4 + 3] = v.w * 0.125f;
    }

    float m_i[4], l_i[4], o_acc[4][4];
#pragma unroll
    for (int i = 0; i < 4; i++) {
        m_i[i] = -1e30f;
        l_i[i] = 0.f;
#pragma unroll
        for (int j = 0; j < 4; j++) o_acc[i][j] = 0.f;
    }

    for (int kt = 0; kt < L_ / BKV; kt++) {
        __syncthreads();  // prior tile's P/V reads complete before overwrite
        const float* Kt = Kbase + (size_t)kt * BKV * D_;
        const float* Vt = Vbase + (size_t)kt * BKV * D_;
        for (int e = tid; e < BKV * 16; e += 256) {
            int r  = e >> 4;
            int c4 = (e & 15) * 4;
            float4 kv = *reinterpret_cast<const float4*>(Kt + (size_t)r * D_ + c4);
            KPs[r * PAD + c4 + 0] = kv.x;
            KPs[r * PAD + c4 + 1] = kv.y;
            KPs[r * PAD + c4 + 2] = kv.z;
            KPs[r * PAD + c4 + 3] = kv.w;
            float4 vv = *reinterpret_cast<const float4*>(Vt + (size_t)r * D_ + c4);
            Vs[r * PAD + c4 + 0] = vv.x;
            Vs[r * PAD + c4 + 1] = vv.y;
            Vs[r * PAD + c4 + 2] = vv.z;
            Vs[r * PAD + c4 + 3] = vv.w;
        }
        __syncthreads();

        // S = (Q * 0.125) @ K^T   (4x4 per thread)
        float s[4][4];
#pragma unroll
        for (int i = 0; i < 4; i++)
#pragma unroll
            for (int j = 0; j < 4; j++) s[i][j] = 0.f;

#pragma unroll 4
        for (int d = 0; d < HD_; d++) {
            float qv[4], kv[4];
#pragma unroll
            for (int i = 0; i < 4; i++) qv[i] = Qs[(ty + 16 * i) * PAD + d];
#pragma unroll
            for (int j = 0; j < 4; j++) kv[j] = KPs[(tx + 16 * j) * PAD + d];
#pragma unroll
            for (int i = 0; i < 4; i++)
#pragma unroll
                for (int j = 0; j < 4; j++)
                    s[i][j] += qv[i] * kv[j];
        }

        // Online softmax update
        float p[4][4];
#pragma unroll
        for (int i = 0; i < 4; i++) {
            float mx = fmaxf(fmaxf(s[i][0], s[i][1]), fmaxf(s[i][2], s[i][3]));
#pragma unroll
            for (int off = 8; off > 0; off >>= 1)
                mx = fmaxf(mx, __shfl_xor_sync(0xffffffffu, mx, off, 16));
            float mnew  = fmaxf(m_i[i], mx);
            float alpha = __expf(m_i[i] - mnew);
            m_i[i] = mnew;
            float rs = 0.f;
#pragma unroll
            for (int j = 0; j < 4; j++) {
                p[i][j] = __expf(s[i][j] - mnew);
                rs += p[i][j];
            }
#pragma unroll
            for (int off = 8; off > 0; off >>= 1)
                rs += __shfl_xor_sync(0xffffffffu, rs, off, 16);
            l_i[i] = l_i[i] * alpha + rs;
#pragma unroll
            for (int j = 0; j < 4; j++) o_acc[i][j] *= alpha;
        }

        __syncthreads();  // all K reads done -> reuse KPs for P
#pragma unroll
        for (int i = 0; i < 4; i++)
#pragma unroll
            for (int j = 0; j < 4; j++)
                KPs[(ty + 16 * i) * PAD + tx + 16 * j] = p[i][j];
        __syncthreads();

        // O += P @ V
#pragma unroll 4
        for (int c = 0; c < BKV; c++) {
            float pr[4], vv[4];
#pragma unroll
            for (int i = 0; i < 4; i++) pr[i] = KPs[(ty + 16 * i) * PAD + c];
#pragma unroll
            for (int j = 0; j < 4; j++) vv[j] = Vs[c * PAD + tx + 16 * j];
#pragma unroll
            for (int i = 0; i < 4; i++)
#pragma unroll
                for (int j = 0; j < 4; j++)
                    o_acc[i][j] += pr[i] * vv[j];
        }
    }

    // Normalize and store
#pragma unroll
    for (int i = 0; i < 4; i++) {
        float inv = 1.f / l_i[i];
#pragma unroll
        for (int j = 0; j < 4; j++) {
            O[(size_t)(b * L_ + q0 + ty + 16 * i) * D_ + h * HD_ + tx + 16 * j] =
                o_acc[i][j] * inv;
        }
    }
}

// ---------------------------------------------------------------------------
// Launch
// ---------------------------------------------------------------------------
extern "C" void kernel_launch(void* const* d_in, const int* in_sizes, int n_in,
                              void* d_out, int out_size)
{
    const float* query = (const float*)d_in[0];
    const float* key   = (const float*)d_in[1];
    const float* value = (const float*)d_in[2];
    const float* Wq    = (const float*)d_in[3];
    const float* bq    = (const float*)d_in[4];
    const float* Wk    = (const float*)d_in[5];
    const float* bk    = (const float*)d_in[6];
    const float* Wv    = (const float*)d_in[7];
    const float* bv    = (const float*)d_in[8];
    const float* Wo    = (const float*)d_in[9];
    const float* bo    = (const float*)d_in[10];
    float* out = (float*)d_out;

    float *gq, *gk, *gv, *gx;
    cudaGetSymbolAddress((void**)&gq, g_Q);
    cudaGetSymbolAddress((void**)&gk, g_K);
    cudaGetSymbolAddress((void**)&gv, g_V);
    cudaGetSymbolAddress((void**)&gx, g_X);

    cudaFuncSetAttribute(flash_kernel,
                         cudaFuncAttributeMaxDynamicSharedMemorySize,
                         FLASH_SMEM_BYTES);

    dim3 ggrid(D_ / BN, MTOT / BM);  // (8, 64)

    gemm_bias_kernel<<<ggrid, 256>>>(query, Wq, bq, gq);
    gemm_bias_kernel<<<ggrid, 256>>>(key,   Wk, bk, gk);
    gemm_bias_kernel<<<ggrid, 256>>>(value, Wv, bv, gv);

    flash_kernel<<<dim3(L_ / BQ, H_, B_), 256, FLASH_SMEM_BYTES>>>(gq, gk, gv, gx);

    gemm_bias_kernel<<<ggrid, 256>>>(gx, Wo, bo, out);
}

// round 6
// speedup vs baseline: 1.5224x; 1.5224x over previous
#include <cuda_runtime.h>
#include <cstdint>

// Problem constants
#define B_   4
#define L_   2048
#define D_   1024
#define H_   16
#define HD_  64
#define MTOT (B_ * L_)   // 8192

// Scratch (device globals; no allocation allowed)
__device__ float g_Q[B_ * L_ * D_];
__device__ float g_K[B_ * L_ * D_];
__device__ float g_V[B_ * L_ * D_];
__device__ float g_X[B_ * L_ * D_];

// ===========================================================================
// tf32 helpers (legacy mma.sync path — works at plain sm_103 target)
// ===========================================================================
__device__ __forceinline__ float to_tf32(float x) {
    float y;
    asm("cvt.rna.tf32.f32 %0, %1;" : "=f"(y) : "f"(x));
    return y;
}

__device__ __forceinline__ void mma_tf32_16x8x8(
    float* d, const uint32_t* a, const uint32_t* b)
{
    asm volatile(
        "mma.sync.aligned.m16n8k8.row.col.f32.tf32.tf32.f32 "
        "{%0,%1,%2,%3}, {%4,%5,%6,%7}, {%8,%9}, {%0,%1,%2,%3};"
        : "+f"(d[0]), "+f"(d[1]), "+f"(d[2]), "+f"(d[3])
        : "r"(a[0]), "r"(a[1]), "r"(a[2]), "r"(a[3]),
          "r"(b[0]), "r"(b[1]));
}

// ===========================================================================
// GEMM: Y[M,N] = X[M,K] @ W[N,K]^T + bias[N]   (M=8192, N=K=1024)
// CTA tile 128x128, BK=32, 8 warps (2x4), warp tile 64x32.
// Smem row stride 36 words -> conflict-free fragment LDS (banks 4r+c).
// Double-buffered smem with register prefetch. tf32 RN via cvt on STS path.
// ===========================================================================
#define GBK 32
#define NCH (D_ / GBK)          // 32
#define LDW 36                  // padded row stride (words)
#define TILE_W (128 * LDW)      // words per (A or B) tile
#define GEMM_SMEM_BYTES (2 * 2 * TILE_W * 4)   // 73728

__global__ __launch_bounds__(256) void gemm_mma_kernel(
    const float* __restrict__ X, const float* __restrict__ W,
    const float* __restrict__ bias, float* __restrict__ Y)
{
    extern __shared__ float sm[];

    const int t    = threadIdx.x;
    const int lane = t & 31;
    const int wid  = t >> 5;
    const int wm   = (wid & 1) * 64;   // warp M offset in tile
    const int wn   = (wid >> 1) * 32;  // warp N offset in tile

    const float* Ag = X + (size_t)blockIdx.y * 128 * D_;
    const float* Bg = W + (size_t)blockIdx.x * 128 * D_;

    float acc[4][4][4];
#pragma unroll
    for (int mf = 0; mf < 4; mf++)
#pragma unroll
        for (int nf = 0; nf < 4; nf++)
#pragma unroll
            for (int r = 0; r < 4; r++) acc[mf][nf][r] = 0.f;

    // gmem->reg loader: 4 float4 per array per chunk
    float4 av[4], bv[4];
    int ldRow[4], ldCol[4];
#pragma unroll
    for (int j = 0; j < 4; j++) {
        const int i = t + j * 256;       // f4 index 0..1023
        ldRow[j] = i >> 3;               // 0..127
        ldCol[j] = (i & 7) * 4;          // 0..28
    }

#define LDG_CHUNK(k0)                                                         \
    do {                                                                      \
        _Pragma("unroll")                                                     \
        for (int j = 0; j < 4; j++) {                                         \
            av[j] = *reinterpret_cast<const float4*>(                         \
                Ag + (size_t)ldRow[j] * D_ + (k0) + ldCol[j]);                \
            bv[j] = *reinterpret_cast<const float4*>(                         \
                Bg + (size_t)ldRow[j] * D_ + (k0) + ldCol[j]);                \
        }                                                                     \
    } while (0)

#define STS_CHUNK(buf)                                                        \
    do {                                                                      \
        float* As_ = sm + (buf) * (2 * TILE_W);                               \
        float* Bs_ = As_ + TILE_W;                                            \
        _Pragma("unroll")                                                     \
        for (int j = 0; j < 4; j++) {                                         \
            float4 a4, b4;                                                    \
            a4.x = to_tf32(av[j].x); a4.y = to_tf32(av[j].y);                 \
            a4.z = to_tf32(av[j].z); a4.w = to_tf32(av[j].w);                 \
            b4.x = to_tf32(bv[j].x); b4.y = to_tf32(bv[j].y);                 \
            b4.z = to_tf32(bv[j].z); b4.w = to_tf32(bv[j].w);                 \
            *reinterpret_cast<float4*>(As_ + ldRow[j] * LDW + ldCol[j]) = a4; \
            *reinterpret_cast<float4*>(Bs_ + ldRow[j] * LDW + ldCol[j]) = b4; \
        }                                                                     \
    } while (0)

    LDG_CHUNK(0);
    STS_CHUNK(0);
    __syncthreads();

    for (int c = 0; c < NCH; c++) {
        if (c + 1 < NCH) LDG_CHUNK((c + 1) * GBK);

        const float* As = sm + (c & 1) * (2 * TILE_W);
        const float* Bs = As + TILE_W;
        const uint32_t* Au = reinterpret_cast<const uint32_t*>(As);
        const uint32_t* Bu = reinterpret_cast<const uint32_t*>(Bs);

        const int qr = lane >> 2;   // 0..7
        const int qc = lane & 3;    // 0..3

#pragma unroll
        for (int ks = 0; ks < GBK / 8; ks++) {
            const int kb = ks * 8;
            uint32_t afr[4][4], bfr[4][2];
#pragma unroll
            for (int mf = 0; mf < 4; mf++) {
                const int r0 = wm + mf * 16 + qr;
                afr[mf][0] = Au[r0 * LDW + kb + qc];
                afr[mf][1] = Au[(r0 + 8) * LDW + kb + qc];
                afr[mf][2] = Au[r0 * LDW + kb + 4 + qc];
                afr[mf][3] = Au[(r0 + 8) * LDW + kb + 4 + qc];
            }
#pragma unroll
            for (int nf = 0; nf < 4; nf++) {
                const int n0 = wn + nf * 8 + qr;
                bfr[nf][0] = Bu[n0 * LDW + kb + qc];
                bfr[nf][1] = Bu[n0 * LDW + kb + 4 + qc];
            }
#pragma unroll
            for (int mf = 0; mf < 4; mf++)
#pragma unroll
                for (int nf = 0; nf < 4; nf++)
                    mma_tf32_16x8x8(acc[mf][nf], afr[mf], bfr[nf]);
        }

        if (c + 1 < NCH) STS_CHUNK((c + 1) & 1);
        __syncthreads();
    }

    // Epilogue: C fragment (row=qr(+8), col=2*qc(+1)) + bias, direct to gmem
    const int gm = blockIdx.y * 128 + wm;
    const int gn = blockIdx.x * 128 + wn;
    const int qr = lane >> 2;
    const int qc = lane & 3;
#pragma unroll
    for (int nf = 0; nf < 4; nf++) {
        const int cc = gn + nf * 8 + 2 * qc;
        const float2 bb = *reinterpret_cast<const float2*>(bias + cc);
#pragma unroll
        for (int mf = 0; mf < 4; mf++) {
            const int r = gm + mf * 16 + qr;
            float2 lo, hi;
            lo.x = acc[mf][nf][0] + bb.x;
            lo.y = acc[mf][nf][1] + bb.y;
            hi.x = acc[mf][nf][2] + bb.x;
            hi.y = acc[mf][nf][3] + bb.y;
            *reinterpret_cast<float2*>(Y + (size_t)r * D_ + cc) = lo;
            *reinterpret_cast<float2*>(Y + (size_t)(r + 8) * D_ + cc) = hi;
        }
    }
}

// ---------------------------------------------------------------------------
// Flash attention (fp32, online softmax) — UNCHANGED from passing R2 kernel.
// ---------------------------------------------------------------------------
#define BQ  64
#define BKV 64
#define PAD 65
#define FLASH_SMEM_BYTES (3 * BQ * PAD * 4)

__global__ __launch_bounds__(256) void flash_kernel(
    const float* __restrict__ Q, const float* __restrict__ K,
    const float* __restrict__ V, float* __restrict__ O)
{
    extern __shared__ float sm[];
    float* Qs  = sm;                 // BQ  * PAD
    float* KPs = sm + BQ * PAD;      // BKV * PAD
    float* Vs  = sm + 2 * BQ * PAD;  // BKV * PAD

    const int tid = threadIdx.x;
    const int tx  = tid & 15;
    const int ty  = tid >> 4;
    const int q0  = blockIdx.x * BQ;
    const int h   = blockIdx.y;
    const int b   = blockIdx.z;

    const float* Qbase = Q + (size_t)(b * L_ + q0) * D_ + h * HD_;
    const float* Kbase = K + (size_t)(b * L_) * D_ + h * HD_;
    const float* Vbase = V + (size_t)(b * L_) * D_ + h * HD_;

    for (int e = tid; e < BQ * 16; e += 256) {
        int r  = e >> 4;
        int c4 = (e & 15) * 4;
        float4 v = *reinterpret_cast<const float4*>(Qbase + (size_t)r * D_ + c4);
        Qs[r * PAD + c4 + 0] = v.x * 0.125f;
        Qs[r * PAD + c4 + 1] = v.y * 0.125f;
        Qs[r * PAD + c4 + 2] = v.z * 0.125f;
        Qs[r * PAD + c4 + 3] = v.w * 0.125f;
    }

    float m_i[4], l_i[4], o_acc[4][4];
#pragma unroll
    for (int i = 0; i < 4; i++) {
        m_i[i] = -1e30f;
        l_i[i] = 0.f;
#pragma unroll
        for (int j = 0; j < 4; j++) o_acc[i][j] = 0.f;
    }

    for (int kt = 0; kt < L_ / BKV; kt++) {
        __syncthreads();
        const float* Kt = Kbase + (size_t)kt * BKV * D_;
        const float* Vt = Vbase + (size_t)kt * BKV * D_;
        for (int e = tid; e < BKV * 16; e += 256) {
            int r  = e >> 4;
            int c4 = (e & 15) * 4;
            float4 kv = *reinterpret_cast<const float4*>(Kt + (size_t)r * D_ + c4);
            KPs[r * PAD + c4 + 0] = kv.x;
            KPs[r * PAD + c4 + 1] = kv.y;
            KPs[r * PAD + c4 + 2] = kv.z;
            KPs[r * PAD + c4 + 3] = kv.w;
            float4 vv = *reinterpret_cast<const float4*>(Vt + (size_t)r * D_ + c4);
            Vs[r * PAD + c4 + 0] = vv.x;
            Vs[r * PAD + c4 + 1] = vv.y;
            Vs[r * PAD + c4 + 2] = vv.z;
            Vs[r * PAD + c4 + 3] = vv.w;
        }
        __syncthreads();

        float s[4][4];
#pragma unroll
        for (int i = 0; i < 4; i++)
#pragma unroll
            for (int j = 0; j < 4; j++) s[i][j] = 0.f;

#pragma unroll 4
        for (int d = 0; d < HD_; d++) {
            float qv[4], kv[4];
#pragma unroll
            for (int i = 0; i < 4; i++) qv[i] = Qs[(ty + 16 * i) * PAD + d];
#pragma unroll
            for (int j = 0; j < 4; j++) kv[j] = KPs[(tx + 16 * j) * PAD + d];
#pragma unroll
            for (int i = 0; i < 4; i++)
#pragma unroll
                for (int j = 0; j < 4; j++)
                    s[i][j] += qv[i] * kv[j];
        }

        float p[4][4];
#pragma unroll
        for (int i = 0; i < 4; i++) {
            float mx = fmaxf(fmaxf(s[i][0], s[i][1]), fmaxf(s[i][2], s[i][3]));
#pragma unroll
            for (int off = 8; off > 0; off >>= 1)
                mx = fmaxf(mx, __shfl_xor_sync(0xffffffffu, mx, off, 16));
            float mnew  = fmaxf(m_i[i], mx);
            float alpha = __expf(m_i[i] - mnew);
            m_i[i] = mnew;
            float rs = 0.f;
#pragma unroll
            for (int j = 0; j < 4; j++) {
                p[i][j] = __expf(s[i][j] - mnew);
                rs += p[i][j];
            }
#pragma unroll
            for (int off = 8; off > 0; off >>= 1)
                rs += __shfl_xor_sync(0xffffffffu, rs, off, 16);
            l_i[i] = l_i[i] * alpha + rs;
#pragma unroll
            for (int j = 0; j < 4; j++) o_acc[i][j] *= alpha;
        }

        __syncthreads();
#pragma unroll
        for (int i = 0; i < 4; i++)
#pragma unroll
            for (int j = 0; j < 4; j++)
                KPs[(ty + 16 * i) * PAD + tx + 16 * j] = p[i][j];
        __syncthreads();

#pragma unroll 4
        for (int c = 0; c < BKV; c++) {
            float pr[4], vv[4];
#pragma unroll
            for (int i = 0; i < 4; i++) pr[i] = KPs[(ty + 16 * i) * PAD + c];
#pragma unroll
            for (int j = 0; j < 4; j++) vv[j] = Vs[c * PAD + tx + 16 * j];
#pragma unroll
            for (int i = 0; i < 4; i++)
#pragma unroll
                for (int j = 0; j < 4; j++)
                    o_acc[i][j] += pr[i] * vv[j];
        }
    }

#pragma unroll
    for (int i = 0; i < 4; i++) {
        float inv = 1.f / l_i[i];
#pragma unroll
        for (int j = 0; j < 4; j++) {
            O[(size_t)(b * L_ + q0 + ty + 16 * i) * D_ + h * HD_ + tx + 16 * j] =
                o_acc[i][j] * inv;
        }
    }
}

// ---------------------------------------------------------------------------
// Launch
// ---------------------------------------------------------------------------
extern "C" void kernel_launch(void* const* d_in, const int* in_sizes, int n_in,
                              void* d_out, int out_size)
{
    const float* query = (const float*)d_in[0];
    const float* key   = (const float*)d_in[1];
    const float* value = (const float*)d_in[2];
    const float* Wq    = (const float*)d_in[3];
    const float* bq    = (const float*)d_in[4];
    const float* Wk    = (const float*)d_in[5];
    const float* bk    = (const float*)d_in[6];
    const float* Wv    = (const float*)d_in[7];
    const float* bv    = (const float*)d_in[8];
    const float* Wo    = (const float*)d_in[9];
    const float* bo    = (const float*)d_in[10];
    float* out = (float*)d_out;

    float *gq, *gk, *gv, *gx;
    cudaGetSymbolAddress((void**)&gq, g_Q);
    cudaGetSymbolAddress((void**)&gk, g_K);
    cudaGetSymbolAddress((void**)&gv, g_V);
    cudaGetSymbolAddress((void**)&gx, g_X);

    cudaFuncSetAttribute(gemm_mma_kernel,
                         cudaFuncAttributeMaxDynamicSharedMemorySize,
                         GEMM_SMEM_BYTES);
    cudaFuncSetAttribute(flash_kernel,
                         cudaFuncAttributeMaxDynamicSharedMemorySize,
                         FLASH_SMEM_BYTES);

    dim3 ggrid(D_ / 128, MTOT / 128);  // (8, 64)

    gemm_mma_kernel<<<ggrid, 256, GEMM_SMEM_BYTES>>>(query, Wq, bq, gq);
    gemm_mma_kernel<<<ggrid, 256, GEMM_SMEM_BYTES>>>(key,   Wk, bk, gk);
    gemm_mma_kernel<<<ggrid, 256, GEMM_SMEM_BYTES>>>(value, Wv, bv, gv);

    flash_kernel<<<dim3(L_ / BQ, H_, B_), 256, FLASH_SMEM_BYTES>>>(gq, gk, gv, gx);

    gemm_mma_kernel<<<ggrid, 256, GEMM_SMEM_BYTES>>>(gx, Wo, bo, out);
}

// round 7
// speedup vs baseline: 2.5047x; 1.6452x over previous
#include <cuda_runtime.h>
#include <cstdint>

// Problem constants
#define B_   4
#define L_   2048
#define D_   1024
#define H_   16
#define HD_  64
#define MTOT (B_ * L_)   // 8192

// Scratch (device globals; no allocation allowed)
__device__ float g_Q[B_ * L_ * D_];
__device__ float g_K[B_ * L_ * D_];
__device__ float g_V[B_ * L_ * D_];
__device__ float g_X[B_ * L_ * D_];

// ===========================================================================
// tf32 helpers (legacy mma.sync path — works at plain sm_103 target)
// ===========================================================================
__device__ __forceinline__ float to_tf32(float x) {
    float y;
    asm("cvt.rna.tf32.f32 %0, %1;" : "=f"(y) : "f"(x));
    return y;
}

__device__ __forceinline__ float ex2_(float x) {
    float y;
    asm("ex2.approx.ftz.f32 %0, %1;" : "=f"(y) : "f"(x));
    return y;
}

__device__ __forceinline__ void mma_tf32_16x8x8(
    float* d, const uint32_t* a, const uint32_t* b)
{
    asm volatile(
        "mma.sync.aligned.m16n8k8.row.col.f32.tf32.tf32.f32 "
        "{%0,%1,%2,%3}, {%4,%5,%6,%7}, {%8,%9}, {%0,%1,%2,%3};"
        : "+f"(d[0]), "+f"(d[1]), "+f"(d[2]), "+f"(d[3])
        : "r"(a[0]), "r"(a[1]), "r"(a[2]), "r"(a[3]),
          "r"(b[0]), "r"(b[1]));
}

// ===========================================================================
// GEMM: Y[M,N] = X[M,K] @ W[N,K]^T + bias[N]  — UNCHANGED (passing R5)
// ===========================================================================
#define GBK 32
#define NCH (D_ / GBK)          // 32
#define LDW 36                  // padded row stride (words)
#define TILE_W (128 * LDW)      // words per (A or B) tile
#define GEMM_SMEM_BYTES (2 * 2 * TILE_W * 4)   // 73728

__global__ __launch_bounds__(256) void gemm_mma_kernel(
    const float* __restrict__ X, const float* __restrict__ W,
    const float* __restrict__ bias, float* __restrict__ Y)
{
    extern __shared__ float sm[];

    const int t    = threadIdx.x;
    const int lane = t & 31;
    const int wid  = t >> 5;
    const int wm   = (wid & 1) * 64;   // warp M offset in tile
    const int wn   = (wid >> 1) * 32;  // warp N offset in tile

    const float* Ag = X + (size_t)blockIdx.y * 128 * D_;
    const float* Bg = W + (size_t)blockIdx.x * 128 * D_;

    float acc[4][4][4];
#pragma unroll
    for (int mf = 0; mf < 4; mf++)
#pragma unroll
        for (int nf = 0; nf < 4; nf++)
#pragma unroll
            for (int r = 0; r < 4; r++) acc[mf][nf][r] = 0.f;

    float4 av[4], bv[4];
    int ldRow[4], ldCol[4];
#pragma unroll
    for (int j = 0; j < 4; j++) {
        const int i = t + j * 256;
        ldRow[j] = i >> 3;
        ldCol[j] = (i & 7) * 4;
    }

#define LDG_CHUNK(k0)                                                         \
    do {                                                                      \
        _Pragma("unroll")                                                     \
        for (int j = 0; j < 4; j++) {                                         \
            av[j] = *reinterpret_cast<const float4*>(                         \
                Ag + (size_t)ldRow[j] * D_ + (k0) + ldCol[j]);                \
            bv[j] = *reinterpret_cast<const float4*>(                         \
                Bg + (size_t)ldRow[j] * D_ + (k0) + ldCol[j]);                \
        }                                                                     \
    } while (0)

#define STS_CHUNK(buf)                                                        \
    do {                                                                      \
        float* As_ = sm + (buf) * (2 * TILE_W);                               \
        float* Bs_ = As_ + TILE_W;                                            \
        _Pragma("unroll")                                                     \
        for (int j = 0; j < 4; j++) {                                         \
            float4 a4, b4;                                                    \
            a4.x = to_tf32(av[j].x); a4.y = to_tf32(av[j].y);                 \
            a4.z = to_tf32(av[j].z); a4.w = to_tf32(av[j].w);                 \
            b4.x = to_tf32(bv[j].x); b4.y = to_tf32(bv[j].y);                 \
            b4.z = to_tf32(bv[j].z); b4.w = to_tf32(bv[j].w);                 \
            *reinterpret_cast<float4*>(As_ + ldRow[j] * LDW + ldCol[j]) = a4; \
            *reinterpret_cast<float4*>(Bs_ + ldRow[j] * LDW + ldCol[j]) = b4; \
        }                                                                     \
    } while (0)

    LDG_CHUNK(0);
    STS_CHUNK(0);
    __syncthreads();

    for (int c = 0; c < NCH; c++) {
        if (c + 1 < NCH) LDG_CHUNK((c + 1) * GBK);

        const float* As = sm + (c & 1) * (2 * TILE_W);
        const float* Bs = As + TILE_W;
        const uint32_t* Au = reinterpret_cast<const uint32_t*>(As);
        const uint32_t* Bu = reinterpret_cast<const uint32_t*>(Bs);

        const int qr = lane >> 2;
        const int qc = lane & 3;

#pragma unroll
        for (int ks = 0; ks < GBK / 8; ks++) {
            const int kb = ks * 8;
            uint32_t afr[4][4], bfr[4][2];
#pragma unroll
            for (int mf = 0; mf < 4; mf++) {
                const int r0 = wm + mf * 16 + qr;
                afr[mf][0] = Au[r0 * LDW + kb + qc];
                afr[mf][1] = Au[(r0 + 8) * LDW + kb + qc];
                afr[mf][2] = Au[r0 * LDW + kb + 4 + qc];
                afr[mf][3] = Au[(r0 + 8) * LDW + kb + 4 + qc];
            }
#pragma unroll
            for (int nf = 0; nf < 4; nf++) {
                const int n0 = wn + nf * 8 + qr;
                bfr[nf][0] = Bu[n0 * LDW + kb + qc];
                bfr[nf][1] = Bu[n0 * LDW + kb + 4 + qc];
            }
#pragma unroll
            for (int mf = 0; mf < 4; mf++)
#pragma unroll
                for (int nf = 0; nf < 4; nf++)
                    mma_tf32_16x8x8(acc[mf][nf], afr[mf], bfr[nf]);
        }

        if (c + 1 < NCH) STS_CHUNK((c + 1) & 1);
        __syncthreads();
    }

    const int gm = blockIdx.y * 128 + wm;
    const int gn = blockIdx.x * 128 + wn;
    const int qr = lane >> 2;
    const int qc = lane & 3;
#pragma unroll
    for (int nf = 0; nf < 4; nf++) {
        const int cc = gn + nf * 8 + 2 * qc;
        const float2 bb = *reinterpret_cast<const float2*>(bias + cc);
#pragma unroll
        for (int mf = 0; mf < 4; mf++) {
            const int r = gm + mf * 16 + qr;
            float2 lo, hi;
            lo.x = acc[mf][nf][0] + bb.x;
            lo.y = acc[mf][nf][1] + bb.y;
            hi.x = acc[mf][nf][2] + bb.x;
            hi.y = acc[mf][nf][3] + bb.y;
            *reinterpret_cast<float2*>(Y + (size_t)r * D_ + cc) = lo;
            *reinterpret_cast<float2*>(Y + (size_t)(r + 8) * D_ + cc) = hi;
        }
    }
}

// ===========================================================================
// Flash attention on mma.sync tf32.
// CTA: 128 Q rows of one (b,h); 8 warps x 16 rows. KV tiles of 64.
// Softmax in base-2 domain: Q pre-scaled by 0.125*log2(e).
// Smem (floats): Ks[64][68] | Vs[64][72] | Ps[8 warps][16][68]
//   (Ps doubles as Q staging [128][68]; per-warp rows coincide).
// Fragment LDS bank patterns are conflict-free (qr*4+qc / qc*8+qr).
// ===========================================================================
#define LDK 68
#define LDV 72
#define LDP 68
#define KS_OFF 0
#define VS_OFF (64 * LDK)                 // 4352
#define PS_OFF (VS_OFF + 64 * LDV)        // 8960
#define FLASH2_SMEM_W (PS_OFF + 128 * LDP)  // 17664 words
#define FLASH2_SMEM_BYTES (FLASH2_SMEM_W * 4)  // 70656
#define QSCALE 0.18033688011112042f       // 0.125 * log2(e)

__global__ __launch_bounds__(256, 2) void flash_mma_kernel(
    const float* __restrict__ Q, const float* __restrict__ K,
    const float* __restrict__ V, float* __restrict__ O)
{
    extern __shared__ float sm[];
    float* Ks = sm + KS_OFF;
    float* Vs = sm + VS_OFF;
    float* Ps = sm + PS_OFF;

    const int tid  = threadIdx.x;
    const int lane = tid & 31;
    const int w    = tid >> 5;       // warp 0..7
    const int qr   = lane >> 2;      // 0..7
    const int qc   = lane & 3;       // 0..3
    const int w16  = w * 16;

    const int q0 = blockIdx.x * 128;
    const int h  = blockIdx.y;
    const int b  = blockIdx.z;

    const float* Qg = Q + (size_t)(b * L_ + q0) * D_ + h * HD_;
    const float* Kg = K + (size_t)(b * L_) * D_ + h * HD_;
    const float* Vg = V + (size_t)(b * L_) * D_ + h * HD_;

    // ---- Stage Q tile [128][64] into Ps region (scaled + tf32), grab frags
    for (int j = 0; j < 8; j++) {
        const int idx = tid + j * 256;        // 0..2047
        const int r   = idx >> 4;             // 0..127
        const int c4  = (idx & 15) * 4;       // 0..60
        float4 v = *reinterpret_cast<const float4*>(Qg + (size_t)r * D_ + c4);
        float* p = Ps + r * LDP + c4;
        p[0] = to_tf32(v.x * QSCALE);
        p[1] = to_tf32(v.y * QSCALE);
        p[2] = to_tf32(v.z * QSCALE);
        p[3] = to_tf32(v.w * QSCALE);
    }
    __syncthreads();

    uint32_t qa[8][4];
    {
        const uint32_t* Pu = reinterpret_cast<const uint32_t*>(Ps);
#pragma unroll
        for (int ks = 0; ks < 8; ks++) {
            const int kb = ks * 8;
            qa[ks][0] = Pu[(w16 + qr) * LDP + kb + qc];
            qa[ks][1] = Pu[(w16 + qr + 8) * LDP + kb + qc];
            qa[ks][2] = Pu[(w16 + qr) * LDP + kb + 4 + qc];
            qa[ks][3] = Pu[(w16 + qr + 8) * LDP + kb + 4 + qc];
        }
    }

    float oacc[8][4];
#pragma unroll
    for (int nf = 0; nf < 8; nf++)
#pragma unroll
        for (int r = 0; r < 4; r++) oacc[nf][r] = 0.f;
    float m0 = -1e30f, m1 = -1e30f, l0 = 0.f, l1 = 0.f;

    float* Pw = Ps + w16 * LDP;                       // per-warp P region
    const uint32_t* Ksu = reinterpret_cast<const uint32_t*>(Ks);
    const uint32_t* Vsu = reinterpret_cast<const uint32_t*>(Vs);
    const uint32_t* Pwu = reinterpret_cast<const uint32_t*>(Pw);

    for (int kt = 0; kt < L_ / 64; kt++) {
        __syncthreads();   // prior tile's K/V reads complete
        const float* Kt = Kg + (size_t)kt * 64 * D_;
        const float* Vt = Vg + (size_t)kt * 64 * D_;
#pragma unroll
        for (int j = 0; j < 4; j++) {
            const int idx = tid + j * 256;    // 0..1023
            const int r   = idx >> 4;         // 0..63
            const int c4  = (idx & 15) * 4;
            float4 kv = *reinterpret_cast<const float4*>(Kt + (size_t)r * D_ + c4);
            float* kp = Ks + r * LDK + c4;
            kp[0] = to_tf32(kv.x); kp[1] = to_tf32(kv.y);
            kp[2] = to_tf32(kv.z); kp[3] = to_tf32(kv.w);
            float4 vv = *reinterpret_cast<const float4*>(Vt + (size_t)r * D_ + c4);
            float* vp = Vs + r * LDV + c4;
            vp[0] = to_tf32(vv.x); vp[1] = to_tf32(vv.y);
            vp[2] = to_tf32(vv.z); vp[3] = to_tf32(vv.w);
        }
        __syncthreads();

        // ---- S = Qs @ K^T  (16 x 64 per warp), log2-domain
        float sacc[8][4];
#pragma unroll
        for (int nf = 0; nf < 8; nf++)
#pragma unroll
            for (int r = 0; r < 4; r++) sacc[nf][r] = 0.f;

#pragma unroll
        for (int ks = 0; ks < 8; ks++) {
            const int kb = ks * 8;
#pragma unroll
            for (int nf = 0; nf < 8; nf++) {
                uint32_t bfr[2];
                bfr[0] = Ksu[(nf * 8 + qr) * LDK + kb + qc];
                bfr[1] = Ksu[(nf * 8 + qr) * LDK + kb + 4 + qc];
                mma_tf32_16x8x8(sacc[nf], qa[ks], bfr);
            }
        }

        // ---- Online softmax (rows qr and qr+8); reduce over qc group (4 lanes)
        {
            float mx0 = -1e30f, mx1 = -1e30f;
#pragma unroll
            for (int nf = 0; nf < 8; nf++) {
                mx0 = fmaxf(mx0, fmaxf(sacc[nf][0], sacc[nf][1]));
                mx1 = fmaxf(mx1, fmaxf(sacc[nf][2], sacc[nf][3]));
            }
            mx0 = fmaxf(mx0, __shfl_xor_sync(0xffffffffu, mx0, 1));
            mx0 = fmaxf(mx0, __shfl_xor_sync(0xffffffffu, mx0, 2));
            mx1 = fmaxf(mx1, __shfl_xor_sync(0xffffffffu, mx1, 1));
            mx1 = fmaxf(mx1, __shfl_xor_sync(0xffffffffu, mx1, 2));

            const float mn0 = fmaxf(m0, mx0);
            const float mn1 = fmaxf(m1, mx1);
            const float a0 = ex2_(m0 - mn0);
            const float a1 = ex2_(m1 - mn1);
            m0 = mn0; m1 = mn1;

            float s0 = 0.f, s1 = 0.f;
#pragma unroll
            for (int nf = 0; nf < 8; nf++) {
                float p0 = ex2_(sacc[nf][0] - mn0);
                float p1 = ex2_(sacc[nf][1] - mn0);
                float p2 = ex2_(sacc[nf][2] - mn1);
                float p3 = ex2_(sacc[nf][3] - mn1);
                s0 += p0 + p1; s1 += p2 + p3;
                sacc[nf][0] = to_tf32(p0); sacc[nf][1] = to_tf32(p1);
                sacc[nf][2] = to_tf32(p2); sacc[nf][3] = to_tf32(p3);
            }
            s0 += __shfl_xor_sync(0xffffffffu, s0, 1);
            s0 += __shfl_xor_sync(0xffffffffu, s0, 2);
            s1 += __shfl_xor_sync(0xffffffffu, s1, 1);
            s1 += __shfl_xor_sync(0xffffffffu, s1, 2);
            l0 = l0 * a0 + s0;
            l1 = l1 * a1 + s1;
#pragma unroll
            for (int nf = 0; nf < 8; nf++) {
                oacc[nf][0] *= a0; oacc[nf][1] *= a0;
                oacc[nf][2] *= a1; oacc[nf][3] *= a1;
            }
        }

        // ---- Store P to per-warp smem (C-layout -> A-layout round trip)
#pragma unroll
        for (int nf = 0; nf < 8; nf++) {
            float2 lo, hi;
            lo.x = sacc[nf][0]; lo.y = sacc[nf][1];
            hi.x = sacc[nf][2]; hi.y = sacc[nf][3];
            *reinterpret_cast<float2*>(Pw + qr * LDP + nf * 8 + 2 * qc) = lo;
            *reinterpret_cast<float2*>(Pw + (qr + 8) * LDP + nf * 8 + 2 * qc) = hi;
        }
        __syncwarp();

        // ---- O += P @ V   (contract over 64 keys)
#pragma unroll
        for (int ks = 0; ks < 8; ks++) {
            const int kb = ks * 8;
            uint32_t pa[4];
            pa[0] = Pwu[qr * LDP + kb + qc];
            pa[1] = Pwu[(qr + 8) * LDP + kb + qc];
            pa[2] = Pwu[qr * LDP + kb + 4 + qc];
            pa[3] = Pwu[(qr + 8) * LDP + kb + 4 + qc];
#pragma unroll
            for (int nf = 0; nf < 8; nf++) {
                uint32_t bfr[2];
                bfr[0] = Vsu[(kb + qc) * LDV + nf * 8 + qr];
                bfr[1] = Vsu[(kb + 4 + qc) * LDV + nf * 8 + qr];
                mma_tf32_16x8x8(oacc[nf], pa, bfr);
            }
        }
    }

    // ---- Epilogue
    const float inv0 = 1.f / l0;
    const float inv1 = 1.f / l1;
    const size_t r0 = (size_t)(b * L_ + q0 + w16 + qr) * D_ + h * HD_;
    const size_t r1 = r0 + 8 * D_;
#pragma unroll
    for (int nf = 0; nf < 8; nf++) {
        const int cc = nf * 8 + 2 * qc;
        float2 lo, hi;
        lo.x = oacc[nf][0] * inv0; lo.y = oacc[nf][1] * inv0;
        hi.x = oacc[nf][2] * inv1; hi.y = oacc[nf][3] * inv1;
        *reinterpret_cast<float2*>(O + r0 + cc) = lo;
        *reinterpret_cast<float2*>(O + r1 + cc) = hi;
    }
}

// ---------------------------------------------------------------------------
// Launch
// ---------------------------------------------------------------------------
extern "C" void kernel_launch(void* const* d_in, const int* in_sizes, int n_in,
                              void* d_out, int out_size)
{
    const float* query = (const float*)d_in[0];
    const float* key   = (const float*)d_in[1];
    const float* value = (const float*)d_in[2];
    const float* Wq    = (const float*)d_in[3];
    const float* bq    = (const float*)d_in[4];
    const float* Wk    = (const float*)d_in[5];
    const float* bk    = (const float*)d_in[6];
    const float* Wv    = (const float*)d_in[7];
    const float* bv    = (const float*)d_in[8];
    const float* Wo    = (const float*)d_in[9];
    const float* bo    = (const float*)d_in[10];
    float* out = (float*)d_out;

    float *gq, *gk, *gv, *gx;
    cudaGetSymbolAddress((void**)&gq, g_Q);
    cudaGetSymbolAddress((void**)&gk, g_K);
    cudaGetSymbolAddress((void**)&gv, g_V);
    cudaGetSymbolAddress((void**)&gx, g_X);

    cudaFuncSetAttribute(gemm_mma_kernel,
                         cudaFuncAttributeMaxDynamicSharedMemorySize,
                         GEMM_SMEM_BYTES);
    cudaFuncSetAttribute(flash_mma_kernel,
                         cudaFuncAttributeMaxDynamicSharedMemorySize,
                         FLASH2_SMEM_BYTES);

    dim3 ggrid(D_ / 128, MTOT / 128);  // (8, 64)

    gemm_mma_kernel<<<ggrid, 256, GEMM_SMEM_BYTES>>>(query, Wq, bq, gq);
    gemm_mma_kernel<<<ggrid, 256, GEMM_SMEM_BYTES>>>(key,   Wk, bk, gk);
    gemm_mma_kernel<<<ggrid, 256, GEMM_SMEM_BYTES>>>(value, Wv, bv, gv);

    flash_mma_kernel<<<dim3(L_ / 128, H_, B_), 256, FLASH2_SMEM_BYTES>>>(gq, gk, gv, gx);

    gemm_mma_kernel<<<ggrid, 256, GEMM_SMEM_BYTES>>>(gx, Wo, bo, out);
}

// round 8
// speedup vs baseline: 4.2909x; 1.7131x over previous
#include <cuda_runtime.h>
#include <cstdint>

// Problem constants
#define B_   4
#define L_   2048
#define D_   1024
#define H_   16
#define HD_  64
#define MTOT (B_ * L_)   // 8192

#define QSCALE 0.18033688011112042f   // 0.125 * log2(e)

// Scratch (device globals; no allocation allowed)
__device__ float g_Q[B_ * L_ * D_];
__device__ float g_K[B_ * L_ * D_];
__device__ float g_V[B_ * L_ * D_];
__device__ float g_X[B_ * L_ * D_];

// ===========================================================================
// tf32 helpers (legacy mma.sync path — works at plain sm_103 target)
// ===========================================================================
__device__ __forceinline__ float to_tf32(float x) {
    float y;
    asm("cvt.rna.tf32.f32 %0, %1;" : "=f"(y) : "f"(x));
    return y;
}

__device__ __forceinline__ float ex2_(float x) {
    float y;
    asm("ex2.approx.ftz.f32 %0, %1;" : "=f"(y) : "f"(x));
    return y;
}

__device__ __forceinline__ void mma_tf32_16x8x8(
    float* d, const uint32_t* a, const uint32_t* b)
{
    asm volatile(
        "mma.sync.aligned.m16n8k8.row.col.f32.tf32.tf32.f32 "
        "{%0,%1,%2,%3}, {%4,%5,%6,%7}, {%8,%9}, {%0,%1,%2,%3};"
        : "+f"(d[0]), "+f"(d[1]), "+f"(d[2]), "+f"(d[3])
        : "r"(a[0]), "r"(a[1]), "r"(a[2]), "r"(a[3]),
          "r"(b[0]), "r"(b[1]));
}

__device__ __forceinline__ uint32_t smem_u32(const void* p) {
    uint32_t a;
    asm("{ .reg .u64 t; cvta.to.shared.u64 t, %1; cvt.u32.u64 %0, t; }"
        : "=r"(a) : "l"(p));
    return a;
}

#define CPASYNC16(dst_u32, src) \
    asm volatile("cp.async.cg.shared.global [%0], [%1], 16;" \
        :: "r"(dst_u32), "l"(src))
#define CPASYNC_COMMIT() asm volatile("cp.async.commit_group;" ::: "memory")
#define CPASYNC_WAIT1()  asm volatile("cp.async.wait_group 1;" ::: "memory")

// ===========================================================================
// GEMM body: Y[M,N] = X[M,K] @ W[N,K]^T + bias[N]   (tile bx,by of 128x128)
// MODE 0: plain fp32 output. MODE 1: output = tf32_round((acc+bias)*scale)
// ===========================================================================
#define GBK 32
#define NCH (D_ / GBK)          // 32
#define LDW 36                  // padded row stride (words)
#define TILE_W (128 * LDW)      // words per (A or B) tile
#define GEMM_SMEM_BYTES (2 * 2 * TILE_W * 4)   // 73728

template <int MODE>
__device__ __forceinline__ void gemm_body(
    const float* __restrict__ X, const float* __restrict__ W,
    const float* __restrict__ bias, float* __restrict__ Y,
    float scale, int bx, int by, float* sm)
{
    const int t    = threadIdx.x;
    const int lane = t & 31;
    const int wid  = t >> 5;
    const int wm   = (wid & 1) * 64;
    const int wn   = (wid >> 1) * 32;

    const float* Ag = X + (size_t)by * 128 * D_;
    const float* Bg = W + (size_t)bx * 128 * D_;

    float acc[4][4][4];
#pragma unroll
    for (int mf = 0; mf < 4; mf++)
#pragma unroll
        for (int nf = 0; nf < 4; nf++)
#pragma unroll
            for (int r = 0; r < 4; r++) acc[mf][nf][r] = 0.f;

    float4 av[4], bv[4];
    int ldRow[4], ldCol[4];
#pragma unroll
    for (int j = 0; j < 4; j++) {
        const int i = t + j * 256;
        ldRow[j] = i >> 3;
        ldCol[j] = (i & 7) * 4;
    }

#define LDG_CHUNK(k0)                                                         \
    do {                                                                      \
        _Pragma("unroll")                                                     \
        for (int j = 0; j < 4; j++) {                                         \
            av[j] = *reinterpret_cast<const float4*>(                         \
                Ag + (size_t)ldRow[j] * D_ + (k0) + ldCol[j]);                \
            bv[j] = *reinterpret_cast<const float4*>(                         \
                Bg + (size_t)ldRow[j] * D_ + (k0) + ldCol[j]);                \
        }                                                                     \
    } while (0)

#define STS_CHUNK(buf)                                                        \
    do {                                                                      \
        float* As_ = sm + (buf) * (2 * TILE_W);                               \
        float* Bs_ = As_ + TILE_W;                                            \
        _Pragma("unroll")                                                     \
        for (int j = 0; j < 4; j++) {                                         \
            float4 a4, b4;                                                    \
            a4.x = to_tf32(av[j].x); a4.y = to_tf32(av[j].y);                 \
            a4.z = to_tf32(av[j].z); a4.w = to_tf32(av[j].w);                 \
            b4.x = to_tf32(bv[j].x); b4.y = to_tf32(bv[j].y);                 \
            b4.z = to_tf32(bv[j].z); b4.w = to_tf32(bv[j].w);                 \
            *reinterpret_cast<float4*>(As_ + ldRow[j] * LDW + ldCol[j]) = a4; \
            *reinterpret_cast<float4*>(Bs_ + ldRow[j] * LDW + ldCol[j]) = b4; \
        }                                                                     \
    } while (0)

    LDG_CHUNK(0);
    STS_CHUNK(0);
    __syncthreads();

    for (int c = 0; c < NCH; c++) {
        if (c + 1 < NCH) LDG_CHUNK((c + 1) * GBK);

        const float* As = sm + (c & 1) * (2 * TILE_W);
        const float* Bs = As + TILE_W;
        const uint32_t* Au = reinterpret_cast<const uint32_t*>(As);
        const uint32_t* Bu = reinterpret_cast<const uint32_t*>(Bs);

        const int qr = lane >> 2;
        const int qc = lane & 3;

#pragma unroll
        for (int ks = 0; ks < GBK / 8; ks++) {
            const int kb = ks * 8;
            uint32_t afr[4][4], bfr[4][2];
#pragma unroll
            for (int mf = 0; mf < 4; mf++) {
                const int r0 = wm + mf * 16 + qr;
                afr[mf][0] = Au[r0 * LDW + kb + qc];
                afr[mf][1] = Au[(r0 + 8) * LDW + kb + qc];
                afr[mf][2] = Au[r0 * LDW + kb + 4 + qc];
                afr[mf][3] = Au[(r0 + 8) * LDW + kb + 4 + qc];
            }
#pragma unroll
            for (int nf = 0; nf < 4; nf++) {
                const int n0 = wn + nf * 8 + qr;
                bfr[nf][0] = Bu[n0 * LDW + kb + qc];
                bfr[nf][1] = Bu[n0 * LDW + kb + 4 + qc];
            }
#pragma unroll
            for (int mf = 0; mf < 4; mf++)
#pragma unroll
                for (int nf = 0; nf < 4; nf++)
                    mma_tf32_16x8x8(acc[mf][nf], afr[mf], bfr[nf]);
        }

        if (c + 1 < NCH) STS_CHUNK((c + 1) & 1);
        __syncthreads();
    }

    const int gm = by * 128 + wm;
    const int gn = bx * 128 + wn;
    const int qr = lane >> 2;
    const int qc = lane & 3;
#pragma unroll
    for (int nf = 0; nf < 4; nf++) {
        const int cc = gn + nf * 8 + 2 * qc;
        const float2 bb = *reinterpret_cast<const float2*>(bias + cc);
#pragma unroll
        for (int mf = 0; mf < 4; mf++) {
            const int r = gm + mf * 16 + qr;
            float2 lo, hi;
            if (MODE == 1) {
                lo.x = to_tf32((acc[mf][nf][0] + bb.x) * scale);
                lo.y = to_tf32((acc[mf][nf][1] + bb.y) * scale);
                hi.x = to_tf32((acc[mf][nf][2] + bb.x) * scale);
                hi.y = to_tf32((acc[mf][nf][3] + bb.y) * scale);
            } else {
                lo.x = acc[mf][nf][0] + bb.x;
                lo.y = acc[mf][nf][1] + bb.y;
                hi.x = acc[mf][nf][2] + bb.x;
                hi.y = acc[mf][nf][3] + bb.y;
            }
            *reinterpret_cast<float2*>(Y + (size_t)r * D_ + cc) = lo;
            *reinterpret_cast<float2*>(Y + (size_t)(r + 8) * D_ + cc) = hi;
        }
    }
#undef LDG_CHUNK
#undef STS_CHUNK
}

// Fused QKV projection: grid.z selects (input, weight, bias, output, scale).
// Q output is pre-scaled by QSCALE and tf32-rounded; K/V tf32-rounded.
__global__ __launch_bounds__(256) void qkv_gemm_kernel(
    const float* __restrict__ q_in, const float* __restrict__ k_in,
    const float* __restrict__ v_in,
    const float* __restrict__ Wq, const float* __restrict__ Wk,
    const float* __restrict__ Wv,
    const float* __restrict__ bq, const float* __restrict__ bk,
    const float* __restrict__ bv,
    float* __restrict__ oq, float* __restrict__ ok, float* __restrict__ ov)
{
    extern __shared__ float sm[];
    const int z = blockIdx.z;
    const float* X  = (z == 0) ? q_in : (z == 1) ? k_in : v_in;
    const float* W  = (z == 0) ? Wq   : (z == 1) ? Wk   : Wv;
    const float* bs = (z == 0) ? bq   : (z == 1) ? bk   : bv;
    float*       Y  = (z == 0) ? oq   : (z == 1) ? ok   : ov;
    const float  sc = (z == 0) ? QSCALE : 1.0f;
    gemm_body<1>(X, W, bs, Y, sc, blockIdx.x, blockIdx.y, sm);
}

__global__ __launch_bounds__(256) void o_gemm_kernel(
    const float* __restrict__ X, const float* __restrict__ W,
    const float* __restrict__ bias, float* __restrict__ Y)
{
    extern __shared__ float sm[];
    gemm_body<0>(X, W, bias, Y, 1.0f, blockIdx.x, blockIdx.y, sm);
}

// ===========================================================================
// Flash attention on mma.sync tf32, cp.async double-buffered K/V.
// Inputs g_Q/g_K/g_V are PRE-ROUNDED tf32 (and g_Q pre-scaled by QSCALE)
// by the QKV GEMM epilogue -> fills are raw byte copies.
// CTA: 128 Q rows of one (b,h); 8 warps x 16 rows. KV tiles of 64.
// Smem (floats): Ps[128][68] (Q staging, then per-warp P)
//              | K0[64][68] K1[64][68] | V0[64][72] V1[64][72]
// ===========================================================================
#define LDK 68
#define LDV 72
#define LDP 68
#define PS_OFF 0
#define K0_OFF (128 * LDP)            // 8704
#define K1_OFF (K0_OFF + 64 * LDK)    // 13056
#define V0_OFF (K1_OFF + 64 * LDK)    // 17408
#define V1_OFF (V0_OFF + 64 * LDV)    // 22016
#define FLASH2_SMEM_W (V1_OFF + 64 * LDV)      // 26624 words
#define FLASH2_SMEM_BYTES (FLASH2_SMEM_W * 4)  // 106496
#define NT (L_ / 64)                  // 32 KV tiles

__global__ __launch_bounds__(256, 2) void flash_mma_kernel(
    const float* __restrict__ Q, const float* __restrict__ K,
    const float* __restrict__ V, float* __restrict__ O)
{
    extern __shared__ float sm[];
    float* Ps = sm + PS_OFF;

    const int tid  = threadIdx.x;
    const int lane = tid & 31;
    const int w    = tid >> 5;
    const int qr   = lane >> 2;
    const int qc   = lane & 3;
    const int w16  = w * 16;

    const int q0 = blockIdx.x * 128;
    const int h  = blockIdx.y;
    const int b  = blockIdx.z;

    const float* Qg = Q + (size_t)(b * L_ + q0) * D_ + h * HD_;
    const float* Kg = K + (size_t)(b * L_) * D_ + h * HD_;
    const float* Vg = V + (size_t)(b * L_) * D_ + h * HD_;

    const uint32_t smem_base = smem_u32(sm);

    // ---- Stage Q tile [128][64] (already scaled+tf32) into Ps, grab frags
    for (int j = 0; j < 8; j++) {
        const int idx = tid + j * 256;
        const int r   = idx >> 4;
        const int c4  = (idx & 15) * 4;
        *reinterpret_cast<float4*>(Ps + r * LDP + c4) =
            *reinterpret_cast<const float4*>(Qg + (size_t)r * D_ + c4);
    }
    __syncthreads();

    uint32_t qa[8][4];
    {
        const uint32_t* Pu = reinterpret_cast<const uint32_t*>(Ps);
#pragma unroll
        for (int ks = 0; ks < 8; ks++) {
            const int kb = ks * 8;
            qa[ks][0] = Pu[(w16 + qr) * LDP + kb + qc];
            qa[ks][1] = Pu[(w16 + qr + 8) * LDP + kb + qc];
            qa[ks][2] = Pu[(w16 + qr) * LDP + kb + 4 + qc];
            qa[ks][3] = Pu[(w16 + qr + 8) * LDP + kb + 4 + qc];
        }
    }

    // ---- cp.async K/V fill (raw 16B chunks; 4 K + 4 V per thread per tile)
    const int fr = tid >> 4;            // 0..15 (row group base)
    const int fc = (tid & 15) * 4;      // 0..60 (float col)
#define FILL_TILE(kt, buf)                                                    \
    do {                                                                      \
        const float* Kt_ = Kg + (size_t)(kt) * 64 * D_;                       \
        const float* Vt_ = Vg + (size_t)(kt) * 64 * D_;                       \
        const uint32_t kb_ = smem_base +                                      \
            (((buf) ? K1_OFF : K0_OFF)) * 4;                                  \
        const uint32_t vb_ = smem_base +                                      \
            (((buf) ? V1_OFF : V0_OFF)) * 4;                                  \
        _Pragma("unroll")                                                     \
        for (int j = 0; j < 4; j++) {                                         \
            const int r_ = fr + j * 16;                                       \
            CPASYNC16(kb_ + (uint32_t)(r_ * LDK + fc) * 4,                    \
                      Kt_ + (size_t)r_ * D_ + fc);                            \
            CPASYNC16(vb_ + (uint32_t)(r_ * LDV + fc) * 4,                    \
                      Vt_ + (size_t)r_ * D_ + fc);                            \
        }                                                                     \
    } while (0)

    FILL_TILE(0, 0); CPASYNC_COMMIT();
    FILL_TILE(1, 1); CPASYNC_COMMIT();

    float oacc[8][4];
#pragma unroll
    for (int nf = 0; nf < 8; nf++)
#pragma unroll
        for (int r = 0; r < 4; r++) oacc[nf][r] = 0.f;
    float m0 = -1e30f, m1 = -1e30f, l0 = 0.f, l1 = 0.f;

    float* Pw = Ps + w16 * LDP;
    const uint32_t* Pwu = reinterpret_cast<const uint32_t*>(Pw);

    for (int kt = 0; kt < NT; kt++) {
        CPASYNC_WAIT1();       // fill of tile kt complete (kt+1 may fly)
        __syncthreads();

        const uint32_t* Ksu = reinterpret_cast<const uint32_t*>(
            sm + ((kt & 1) ? K1_OFF : K0_OFF));
        const uint32_t* Vsu = reinterpret_cast<const uint32_t*>(
            sm + ((kt & 1) ? V1_OFF : V0_OFF));

        // ---- S = Qs @ K^T  (16 x 64 per warp), log2-domain
        float sacc[8][4];
#pragma unroll
        for (int nf = 0; nf < 8; nf++)
#pragma unroll
            for (int r = 0; r < 4; r++) sacc[nf][r] = 0.f;

#pragma unroll
        for (int ks = 0; ks < 8; ks++) {
            const int kb = ks * 8;
#pragma unroll
            for (int nf = 0; nf < 8; nf++) {
                uint32_t bfr[2];
                bfr[0] = Ksu[(nf * 8 + qr) * LDK + kb + qc];
                bfr[1] = Ksu[(nf * 8 + qr) * LDK + kb + 4 + qc];
                mma_tf32_16x8x8(sacc[nf], qa[ks], bfr);
            }
        }

        // ---- Online softmax (rows qr, qr+8); reduce over qc group
        {
            float mx0 = -1e30f, mx1 = -1e30f;
#pragma unroll
            for (int nf = 0; nf < 8; nf++) {
                mx0 = fmaxf(mx0, fmaxf(sacc[nf][0], sacc[nf][1]));
                mx1 = fmaxf(mx1, fmaxf(sacc[nf][2], sacc[nf][3]));
            }
            mx0 = fmaxf(mx0, __shfl_xor_sync(0xffffffffu, mx0, 1));
            mx0 = fmaxf(mx0, __shfl_xor_sync(0xffffffffu, mx0, 2));
            mx1 = fmaxf(mx1, __shfl_xor_sync(0xffffffffu, mx1, 1));
            mx1 = fmaxf(mx1, __shfl_xor_sync(0xffffffffu, mx1, 2));

            const float mn0 = fmaxf(m0, mx0);
            const float mn1 = fmaxf(m1, mx1);
            const float a0 = ex2_(m0 - mn0);
            const float a1 = ex2_(m1 - mn1);
            m0 = mn0; m1 = mn1;

            float s0 = 0.f, s1 = 0.f;
#pragma unroll
            for (int nf = 0; nf < 8; nf++) {
                float p0 = ex2_(sacc[nf][0] - mn0);
                float p1 = ex2_(sacc[nf][1] - mn0);
                float p2 = ex2_(sacc[nf][2] - mn1);
                float p3 = ex2_(sacc[nf][3] - mn1);
                s0 += p0 + p1; s1 += p2 + p3;
                sacc[nf][0] = to_tf32(p0); sacc[nf][1] = to_tf32(p1);
                sacc[nf][2] = to_tf32(p2); sacc[nf][3] = to_tf32(p3);
            }
            s0 += __shfl_xor_sync(0xffffffffu, s0, 1);
            s0 += __shfl_xor_sync(0xffffffffu, s0, 2);
            s1 += __shfl_xor_sync(0xffffffffu, s1, 1);
            s1 += __shfl_xor_sync(0xffffffffu, s1, 2);
            l0 = l0 * a0 + s0;
            l1 = l1 * a1 + s1;
#pragma unroll
            for (int nf = 0; nf < 8; nf++) {
                oacc[nf][0] *= a0; oacc[nf][1] *= a0;
                oacc[nf][2] *= a1; oacc[nf][3] *= a1;
            }
        }

        // ---- Store P to per-warp smem (C-layout -> A-layout round trip)
#pragma unroll
        for (int nf = 0; nf < 8; nf++) {
            float2 lo, hi;
            lo.x = sacc[nf][0]; lo.y = sacc[nf][1];
            hi.x = sacc[nf][2]; hi.y = sacc[nf][3];
            *reinterpret_cast<float2*>(Pw + qr * LDP + nf * 8 + 2 * qc) = lo;
            *reinterpret_cast<float2*>(Pw + (qr + 8) * LDP + nf * 8 + 2 * qc) = hi;
        }
        __syncwarp();

        // ---- O += P @ V
#pragma unroll
        for (int ks = 0; ks < 8; ks++) {
            const int kb = ks * 8;
            uint32_t pa[4];
            pa[0] = Pwu[qr * LDP + kb + qc];
            pa[1] = Pwu[(qr + 8) * LDP + kb + qc];
            pa[2] = Pwu[qr * LDP + kb + 4 + qc];
            pa[3] = Pwu[(qr + 8) * LDP + kb + 4 + qc];
#pragma unroll
            for (int nf = 0; nf < 8; nf++) {
                uint32_t bfr[2];
                bfr[0] = Vsu[(kb + qc) * LDV + nf * 8 + qr];
                bfr[1] = Vsu[(kb + 4 + qc) * LDV + nf * 8 + qr];
                mma_tf32_16x8x8(oacc[nf], pa, bfr);
            }
        }

        // ---- Prefetch tile kt+2 into the buffer just consumed
        __syncthreads();
        if (kt + 2 < NT) FILL_TILE(kt + 2, (kt & 1));
        CPASYNC_COMMIT();
    }

    // ---- Epilogue
    const float inv0 = 1.f / l0;
    const float inv1 = 1.f / l1;
    const size_t r0 = (size_t)(b * L_ + q0 + w16 + qr) * D_ + h * HD_;
    const size_t r1 = r0 + 8 * D_;
#pragma unroll
    for (int nf = 0; nf < 8; nf++) {
        const int cc = nf * 8 + 2 * qc;
        float2 lo, hi;
        lo.x = oacc[nf][0] * inv0; lo.y = oacc[nf][1] * inv0;
        hi.x = oacc[nf][2] * inv1; hi.y = oacc[nf][3] * inv1;
        *reinterpret_cast<float2*>(O + r0 + cc) = lo;
        *reinterpret_cast<float2*>(O + r1 + cc) = hi;
    }
#undef FILL_TILE
}

// ---------------------------------------------------------------------------
// Launch
// ---------------------------------------------------------------------------
extern "C" void kernel_launch(void* const* d_in, const int* in_sizes, int n_in,
                              void* d_out, int out_size)
{
    const float* query = (const float*)d_in[0];
    const float* key   = (const float*)d_in[1];
    const float* value = (const float*)d_in[2];
    const float* Wq    = (const float*)d_in[3];
    const float* bq    = (const float*)d_in[4];
    const float* Wk    = (const float*)d_in[5];
    const float* bk    = (const float*)d_in[6];
    const float* Wv    = (const float*)d_in[7];
    const float* bv    = (const float*)d_in[8];
    const float* Wo    = (const float*)d_in[9];
    const float* bo    = (const float*)d_in[10];
    float* out = (float*)d_out;

    float *gq, *gk, *gv, *gx;
    cudaGetSymbolAddress((void**)&gq, g_Q);
    cudaGetSymbolAddress((void**)&gk, g_K);
    cudaGetSymbolAddress((void**)&gv, g_V);
    cudaGetSymbolAddress((void**)&gx, g_X);

    cudaFuncSetAttribute(qkv_gemm_kernel,
                         cudaFuncAttributeMaxDynamicSharedMemorySize,
                         GEMM_SMEM_BYTES);
    cudaFuncSetAttribute(o_gemm_kernel,
                         cudaFuncAttributeMaxDynamicSharedMemorySize,
                         GEMM_SMEM_BYTES);
    cudaFuncSetAttribute(flash_mma_kernel,
                         cudaFuncAttributeMaxDynamicSharedMemorySize,
                         FLASH2_SMEM_BYTES);

    qkv_gemm_kernel<<<dim3(D_ / 128, MTOT / 128, 3), 256, GEMM_SMEM_BYTES>>>(
        query, key, value, Wq, Wk, Wv, bq, bk, bv, gq, gk, gv);

    flash_mma_kernel<<<dim3(L_ / 128, H_, B_), 256, FLASH2_SMEM_BYTES>>>(
        gq, gk, gv, gx);

    o_gemm_kernel<<<dim3(D_ / 128, MTOT / 128), 256, GEMM_SMEM_BYTES>>>(
        gx, Wo, bo, out);
}

// round 9
// speedup vs baseline: 4.6925x; 1.0936x over previous
#include <cuda_runtime.h>
#include <cstdint>

// Problem constants
#define B_   4
#define L_   2048
#define D_   1024
#define H_   16
#define HD_  64
#define MTOT (B_ * L_)   // 8192

#define QSCALE 0.18033688011112042f   // 0.125 * log2(e)

// Scratch (device globals; no allocation allowed)
__device__ float g_Q[MTOT * D_];
__device__ float g_K[MTOT * D_];
__device__ float g_V[MTOT * D_];
__device__ float g_X[MTOT * D_];
// Pre-rounded (tf32) operand copies
__device__ float g_QI[MTOT * D_];
__device__ float g_KI[MTOT * D_];
__device__ float g_VI[MTOT * D_];
__device__ float g_Wq[D_ * D_];
__device__ float g_Wk[D_ * D_];
__device__ float g_Wv[D_ * D_];
__device__ float g_Wo[D_ * D_];

// ===========================================================================
// Helpers
// ===========================================================================
__device__ __forceinline__ float to_tf32(float x) {
    float y;
    asm("cvt.rna.tf32.f32 %0, %1;" : "=f"(y) : "f"(x));
    return y;
}

__device__ __forceinline__ float ex2_(float x) {
    float y;
    asm("ex2.approx.ftz.f32 %0, %1;" : "=f"(y) : "f"(x));
    return y;
}

__device__ __forceinline__ void mma_tf32_16x8x8(
    float* d, const uint32_t* a, const uint32_t* b)
{
    asm volatile(
        "mma.sync.aligned.m16n8k8.row.col.f32.tf32.tf32.f32 "
        "{%0,%1,%2,%3}, {%4,%5,%6,%7}, {%8,%9}, {%0,%1,%2,%3};"
        : "+f"(d[0]), "+f"(d[1]), "+f"(d[2]), "+f"(d[3])
        : "r"(a[0]), "r"(a[1]), "r"(a[2]), "r"(a[3]),
          "r"(b[0]), "r"(b[1]));
}

__device__ __forceinline__ uint32_t smem_u32(const void* p) {
    uint32_t a;
    asm("{ .reg .u64 t; cvta.to.shared.u64 t, %1; cvt.u32.u64 %0, t; }"
        : "=r"(a) : "l"(p));
    return a;
}

#define CPASYNC16(dst_u32, src) \
    asm volatile("cp.async.cg.shared.global [%0], [%1], 16;" \
        :: "r"(dst_u32), "l"(src))
#define CPASYNC_COMMIT() asm volatile("cp.async.commit_group;" ::: "memory")
#define CPASYNC_WAIT1()  asm volatile("cp.async.wait_group 1;" ::: "memory")

// ===========================================================================
// Pre-round pass: tf32-round inputs and weights into scratch.
// grid = (8192, 7); z selects tensor. Bandwidth-bound, ~35us.
// ===========================================================================
__global__ __launch_bounds__(256) void preround_kernel(
    const float* __restrict__ q, const float* __restrict__ k,
    const float* __restrict__ v,
    const float* __restrict__ wq, const float* __restrict__ wk,
    const float* __restrict__ wv, const float* __restrict__ wo)
{
    const int z = blockIdx.y;
    const float* s; float* d; int n;
    switch (z) {
        case 0: s = q;  d = g_QI; n = MTOT * D_; break;
        case 1: s = k;  d = g_KI; n = MTOT * D_; break;
        case 2: s = v;  d = g_VI; n = MTOT * D_; break;
        case 3: s = wq; d = g_Wq; n = D_ * D_;   break;
        case 4: s = wk; d = g_Wk; n = D_ * D_;   break;
        case 5: s = wv; d = g_Wv; n = D_ * D_;   break;
        default: s = wo; d = g_Wo; n = D_ * D_;  break;
    }
    const int idx = (blockIdx.x * 256 + threadIdx.x) * 4;
    if (idx < n) {
        float4 x = *reinterpret_cast<const float4*>(s + idx);
        x.x = to_tf32(x.x); x.y = to_tf32(x.y);
        x.z = to_tf32(x.z); x.w = to_tf32(x.w);
        *reinterpret_cast<float4*>(d + idx) = x;
    }
}

// ===========================================================================
// GEMM body: Y[M,N] = X[M,K] @ W[N,K]^T + bias[N]   (tile bx,by of 128x128)
// Operands are PRE-ROUNDED tf32 -> cp.async raw copies, 3-stage pipeline,
// one __syncthreads per chunk. 2 CTAs/SM.
// MODE 0: plain fp32 output. MODE 1: output = tf32_round((acc+bias)*scale)
// ===========================================================================
#define GBK 32
#define NCH (D_ / GBK)          // 32
#define LDW 36                  // padded row stride (words)
#define TILE_W (128 * LDW)      // 4608 words per operand tile
#define STG_W (2 * TILE_W)      // 9216 words per stage (A+B)
#define GEMM_SMEM_BYTES (3 * STG_W * 4)   // 110592

template <int MODE>
__device__ __forceinline__ void gemm_body(
    const float* __restrict__ X, const float* __restrict__ W,
    const float* __restrict__ bias, float* __restrict__ Y,
    float scale, int bx, int by, float* sm)
{
    const int t    = threadIdx.x;
    const int lane = t & 31;
    const int wid  = t >> 5;
    const int wm   = (wid & 1) * 64;
    const int wn   = (wid >> 1) * 32;

    const float* Ag = X + (size_t)by * 128 * D_;
    const float* Bg = W + (size_t)bx * 128 * D_;

    const uint32_t sbase = smem_u32(sm);

    float acc[4][4][4];
#pragma unroll
    for (int mf = 0; mf < 4; mf++)
#pragma unroll
        for (int nf = 0; nf < 4; nf++)
#pragma unroll
            for (int r = 0; r < 4; r++) acc[mf][nf][r] = 0.f;

#define FILLG(k0, stg)                                                        \
    do {                                                                      \
        const uint32_t ab_ = sbase + (uint32_t)(stg) * (STG_W * 4);           \
        const uint32_t bb_ = ab_ + TILE_W * 4;                                \
        _Pragma("unroll")                                                     \
        for (int j = 0; j < 4; j++) {                                         \
            const int i_ = t + j * 256;                                       \
            const int r_ = i_ >> 3;                                           \
            const int c_ = (i_ & 7) * 4;                                      \
            CPASYNC16(ab_ + (uint32_t)(r_ * LDW + c_) * 4,                    \
                      Ag + (size_t)r_ * D_ + (k0) + c_);                      \
            CPASYNC16(bb_ + (uint32_t)(r_ * LDW + c_) * 4,                    \
                      Bg + (size_t)r_ * D_ + (k0) + c_);                      \
        }                                                                     \
    } while (0)

    FILLG(0, 0);   CPASYNC_COMMIT();
    FILLG(GBK, 1); CPASYNC_COMMIT();

    const int qr = lane >> 2;
    const int qc = lane & 3;

    int stg = 0;
    for (int c = 0; c < NCH; c++) {
        CPASYNC_WAIT1();       // chunk c resident (chunk c+1 may be in flight)
        __syncthreads();

        const uint32_t* Au = reinterpret_cast<const uint32_t*>(sm + stg * STG_W);
        const uint32_t* Bu = Au + TILE_W;

#pragma unroll
        for (int ks = 0; ks < GBK / 8; ks++) {
            const int kb = ks * 8;
            uint32_t afr[4][4], bfr[4][2];
#pragma unroll
            for (int mf = 0; mf < 4; mf++) {
                const int r0 = wm + mf * 16 + qr;
                afr[mf][0] = Au[r0 * LDW + kb + qc];
                afr[mf][1] = Au[(r0 + 8) * LDW + kb + qc];
                afr[mf][2] = Au[r0 * LDW + kb + 4 + qc];
                afr[mf][3] = Au[(r0 + 8) * LDW + kb + 4 + qc];
            }
#pragma unroll
            for (int nf = 0; nf < 4; nf++) {
                const int n0 = wn + nf * 8 + qr;
                bfr[nf][0] = Bu[n0 * LDW + kb + qc];
                bfr[nf][1] = Bu[n0 * LDW + kb + 4 + qc];
            }
#pragma unroll
            for (int mf = 0; mf < 4; mf++)
#pragma unroll
                for (int nf = 0; nf < 4; nf++)
                    mma_tf32_16x8x8(acc[mf][nf], afr[mf], bfr[nf]);
        }

        // Refill the stage consumed at c-1 (safe: all threads passed the
        // barrier above, so no one still reads stage (c-1)%3).
        const int cn = c + 2;
        if (cn < NCH) {
            const int ns = (stg + 2 > 2) ? stg - 1 : stg + 2;
            FILLG(cn * GBK, ns);
        }
        CPASYNC_COMMIT();
        stg = (stg + 1 > 2) ? 0 : stg + 1;
    }

    const int gm = by * 128 + wm;
    const int gn = bx * 128 + wn;
#pragma unroll
    for (int nf = 0; nf < 4; nf++) {
        const int cc = gn + nf * 8 + 2 * qc;
        const float2 bb = *reinterpret_cast<const float2*>(bias + cc);
#pragma unroll
        for (int mf = 0; mf < 4; mf++) {
            const int r = gm + mf * 16 + qr;
            float2 lo, hi;
            if (MODE == 1) {
                lo.x = to_tf32((acc[mf][nf][0] + bb.x) * scale);
                lo.y = to_tf32((acc[mf][nf][1] + bb.y) * scale);
                hi.x = to_tf32((acc[mf][nf][2] + bb.x) * scale);
                hi.y = to_tf32((acc[mf][nf][3] + bb.y) * scale);
            } else {
                lo.x = acc[mf][nf][0] + bb.x;
                lo.y = acc[mf][nf][1] + bb.y;
                hi.x = acc[mf][nf][2] + bb.x;
                hi.y = acc[mf][nf][3] + bb.y;
            }
            *reinterpret_cast<float2*>(Y + (size_t)r * D_ + cc) = lo;
            *reinterpret_cast<float2*>(Y + (size_t)(r + 8) * D_ + cc) = hi;
        }
    }
#undef FILLG
}

// Fused QKV projection on pre-rounded operands.
__global__ __launch_bounds__(256, 2) void qkv_gemm_kernel(
    const float* __restrict__ qi, const float* __restrict__ ki,
    const float* __restrict__ vi,
    const float* __restrict__ wq, const float* __restrict__ wk,
    const float* __restrict__ wv,
    const float* __restrict__ bq, const float* __restrict__ bk,
    const float* __restrict__ bv,
    float* __restrict__ oq, float* __restrict__ ok, float* __restrict__ ov)
{
    extern __shared__ float sm[];
    const int z = blockIdx.z;
    const float* X  = (z == 0) ? qi : (z == 1) ? ki : vi;
    const float* W  = (z == 0) ? wq : (z == 1) ? wk : wv;
    const float* bs = (z == 0) ? bq : (z == 1) ? bk : bv;
    float*       Y  = (z == 0) ? oq : (z == 1) ? ok : ov;
    const float  sc = (z == 0) ? QSCALE : 1.0f;
    gemm_body<1>(X, W, bs, Y, sc, blockIdx.x, blockIdx.y, sm);
}

__global__ __launch_bounds__(256, 2) void o_gemm_kernel(
    const float* __restrict__ X, const float* __restrict__ W,
    const float* __restrict__ bias, float* __restrict__ Y)
{
    extern __shared__ float sm[];
    gemm_body<0>(X, W, bias, Y, 1.0f, blockIdx.x, blockIdx.y, sm);
}

// ===========================================================================
// Flash attention on mma.sync tf32, cp.async double-buffered K/V.
// (Unchanged from passing R7 except: epilogue tf32-rounds the output so the
//  O-projection GEMM can consume it raw.)
// ===========================================================================
#define LDK 68
#define LDV 72
#define LDP 68
#define PS_OFF 0
#define K0_OFF (128 * LDP)            // 8704
#define K1_OFF (K0_OFF + 64 * LDK)    // 13056
#define V0_OFF (K1_OFF + 64 * LDK)    // 17408
#define V1_OFF (V0_OFF + 64 * LDV)    // 22016
#define FLASH2_SMEM_W (V1_OFF + 64 * LDV)      // 26624 words
#define FLASH2_SMEM_BYTES (FLASH2_SMEM_W * 4)  // 106496
#define NT (L_ / 64)                  // 32 KV tiles

__global__ __launch_bounds__(256, 2) void flash_mma_kernel(
    const float* __restrict__ Q, const float* __restrict__ K,
    const float* __restrict__ V, float* __restrict__ O)
{
    extern __shared__ float sm[];
    float* Ps = sm + PS_OFF;

    const int tid  = threadIdx.x;
    const int lane = tid & 31;
    const int w    = tid >> 5;
    const int qr   = lane >> 2;
    const int qc   = lane & 3;
    const int w16  = w * 16;

    const int q0 = blockIdx.x * 128;
    const int h  = blockIdx.y;
    const int b  = blockIdx.z;

    const float* Qg = Q + (size_t)(b * L_ + q0) * D_ + h * HD_;
    const float* Kg = K + (size_t)(b * L_) * D_ + h * HD_;
    const float* Vg = V + (size_t)(b * L_) * D_ + h * HD_;

    const uint32_t smem_base = smem_u32(sm);

    for (int j = 0; j < 8; j++) {
        const int idx = tid + j * 256;
        const int r   = idx >> 4;
        const int c4  = (idx & 15) * 4;
        *reinterpret_cast<float4*>(Ps + r * LDP + c4) =
            *reinterpret_cast<const float4*>(Qg + (size_t)r * D_ + c4);
    }
    __syncthreads();

    uint32_t qa[8][4];
    {
        const uint32_t* Pu = reinterpret_cast<const uint32_t*>(Ps);
#pragma unroll
        for (int ks = 0; ks < 8; ks++) {
            const int kb = ks * 8;
            qa[ks][0] = Pu[(w16 + qr) * LDP + kb + qc];
            qa[ks][1] = Pu[(w16 + qr + 8) * LDP + kb + qc];
            qa[ks][2] = Pu[(w16 + qr) * LDP + kb + 4 + qc];
            qa[ks][3] = Pu[(w16 + qr + 8) * LDP + kb + 4 + qc];
        }
    }

    const int fr = tid >> 4;
    const int fc = (tid & 15) * 4;
#define FILL_TILE(kt, buf)                                                    \
    do {                                                                      \
        const float* Kt_ = Kg + (size_t)(kt) * 64 * D_;                       \
        const float* Vt_ = Vg + (size_t)(kt) * 64 * D_;                       \
        const uint32_t kb_ = smem_base + (((buf) ? K1_OFF : K0_OFF)) * 4;     \
        const uint32_t vb_ = smem_base + (((buf) ? V1_OFF : V0_OFF)) * 4;     \
        _Pragma("unroll")                                                     \
        for (int j = 0; j < 4; j++) {                                         \
            const int r_ = fr + j * 16;                                       \
            CPASYNC16(kb_ + (uint32_t)(r_ * LDK + fc) * 4,                    \
                      Kt_ + (size_t)r_ * D_ + fc);                            \
            CPASYNC16(vb_ + (uint32_t)(r_ * LDV + fc) * 4,                    \
                      Vt_ + (size_t)r_ * D_ + fc);                            \
        }                                                                     \
    } while (0)

    FILL_TILE(0, 0); CPASYNC_COMMIT();
    FILL_TILE(1, 1); CPASYNC_COMMIT();

    float oacc[8][4];
#pragma unroll
    for (int nf = 0; nf < 8; nf++)
#pragma unroll
        for (int r = 0; r < 4; r++) oacc[nf][r] = 0.f;
    float m0 = -1e30f, m1 = -1e30f, l0 = 0.f, l1 = 0.f;

    float* Pw = Ps + w16 * LDP;
    const uint32_t* Pwu = reinterpret_cast<const uint32_t*>(Pw);

    for (int kt = 0; kt < NT; kt++) {
        CPASYNC_WAIT1();
        __syncthreads();

        const uint32_t* Ksu = reinterpret_cast<const uint32_t*>(
            sm + ((kt & 1) ? K1_OFF : K0_OFF));
        const uint32_t* Vsu = reinterpret_cast<const uint32_t*>(
            sm + ((kt & 1) ? V1_OFF : V0_OFF));

        float sacc[8][4];
#pragma unroll
        for (int nf = 0; nf < 8; nf++)
#pragma unroll
            for (int r = 0; r < 4; r++) sacc[nf][r] = 0.f;

#pragma unroll
        for (int ks = 0; ks < 8; ks++) {
            const int kb = ks * 8;
#pragma unroll
            for (int nf = 0; nf < 8; nf++) {
                uint32_t bfr[2];
                bfr[0] = Ksu[(nf * 8 + qr) * LDK + kb + qc];
                bfr[1] = Ksu[(nf * 8 + qr) * LDK + kb + 4 + qc];
                mma_tf32_16x8x8(sacc[nf], qa[ks], bfr);
            }
        }

        {
            float mx0 = -1e30f, mx1 = -1e30f;
#pragma unroll
            for (int nf = 0; nf < 8; nf++) {
                mx0 = fmaxf(mx0, fmaxf(sacc[nf][0], sacc[nf][1]));
                mx1 = fmaxf(mx1, fmaxf(sacc[nf][2], sacc[nf][3]));
            }
            mx0 = fmaxf(mx0, __shfl_xor_sync(0xffffffffu, mx0, 1));
            mx0 = fmaxf(mx0, __shfl_xor_sync(0xffffffffu, mx0, 2));
            mx1 = fmaxf(mx1, __shfl_xor_sync(0xffffffffu, mx1, 1));
            mx1 = fmaxf(mx1, __shfl_xor_sync(0xffffffffu, mx1, 2));

            const float mn0 = fmaxf(m0, mx0);
            const float mn1 = fmaxf(m1, mx1);
            const float a0 = ex2_(m0 - mn0);
            const float a1 = ex2_(m1 - mn1);
            m0 = mn0; m1 = mn1;

            float s0 = 0.f, s1 = 0.f;
#pragma unroll
            for (int nf = 0; nf < 8; nf++) {
                float p0 = ex2_(sacc[nf][0] - mn0);
                float p1 = ex2_(sacc[nf][1] - mn0);
                float p2 = ex2_(sacc[nf][2] - mn1);
                float p3 = ex2_(sacc[nf][3] - mn1);
                s0 += p0 + p1; s1 += p2 + p3;
                sacc[nf][0] = to_tf32(p0); sacc[nf][1] = to_tf32(p1);
                sacc[nf][2] = to_tf32(p2); sacc[nf][3] = to_tf32(p3);
            }
            s0 += __shfl_xor_sync(0xffffffffu, s0, 1);
            s0 += __shfl_xor_sync(0xffffffffu, s0, 2);
            s1 += __shfl_xor_sync(0xffffffffu, s1, 1);
            s1 += __shfl_xor_sync(0xffffffffu, s1, 2);
            l0 = l0 * a0 + s0;
            l1 = l1 * a1 + s1;
#pragma unroll
            for (int nf = 0; nf < 8; nf++) {
                oacc[nf][0] *= a0; oacc[nf][1] *= a0;
                oacc[nf][2] *= a1; oacc[nf][3] *= a1;
            }
        }

#pragma unroll
        for (int nf = 0; nf < 8; nf++) {
            float2 lo, hi;
            lo.x = sacc[nf][0]; lo.y = sacc[nf][1];
            hi.x = sacc[nf][2]; hi.y = sacc[nf][3];
            *reinterpret_cast<float2*>(Pw + qr * LDP + nf * 8 + 2 * qc) = lo;
            *reinterpret_cast<float2*>(Pw + (qr + 8) * LDP + nf * 8 + 2 * qc) = hi;
        }
        __syncwarp();

#pragma unroll
        for (int ks = 0; ks < 8; ks++) {
            const int kb = ks * 8;
            uint32_t pa[4];
            pa[0] = Pwu[qr * LDP + kb + qc];
            pa[1] = Pwu[(qr + 8) * LDP + kb + qc];
            pa[2] = Pwu[qr * LDP + kb + 4 + qc];
            pa[3] = Pwu[(qr + 8) * LDP + kb + 4 + qc];
#pragma unroll
            for (int nf = 0; nf < 8; nf++) {
                uint32_t bfr[2];
                bfr[0] = Vsu[(kb + qc) * LDV + nf * 8 + qr];
                bfr[1] = Vsu[(kb + 4 + qc) * LDV + nf * 8 + qr];
                mma_tf32_16x8x8(oacc[nf], pa, bfr);
            }
        }

        __syncthreads();
        if (kt + 2 < NT) FILL_TILE(kt + 2, (kt & 1));
        CPASYNC_COMMIT();
    }

    // Epilogue: tf32-round so o_gemm consumes raw bytes.
    const float inv0 = 1.f / l0;
    const float inv1 = 1.f / l1;
    const size_t r0 = (size_t)(b * L_ + q0 + w16 + qr) * D_ + h * HD_;
    const size_t r1 = r0 + 8 * D_;
#pragma unroll
    for (int nf = 0; nf < 8; nf++) {
        const int cc = nf * 8 + 2 * qc;
        float2 lo, hi;
        lo.x = to_tf32(oacc[nf][0] * inv0); lo.y = to_tf32(oacc[nf][1] * inv0);
        hi.x = to_tf32(oacc[nf][2] * inv1); hi.y = to_tf32(oacc[nf][3] * inv1);
        *reinterpret_cast<float2*>(O + r0 + cc) = lo;
        *reinterpret_cast<float2*>(O + r1 + cc) = hi;
    }
#undef FILL_TILE
}

// ---------------------------------------------------------------------------
// Launch
// ---------------------------------------------------------------------------
extern "C" void kernel_launch(void* const* d_in, const int* in_sizes, int n_in,
                              void* d_out, int out_size)
{
    const float* query = (const float*)d_in[0];
    const float* key   = (const float*)d_in[1];
    const float* value = (const float*)d_in[2];
    const float* Wq    = (const float*)d_in[3];
    const float* bq    = (const float*)d_in[4];
    const float* Wk    = (const float*)d_in[5];
    const float* bk    = (const float*)d_in[6];
    const float* Wv    = (const float*)d_in[7];
    const float* bv    = (const float*)d_in[8];
    const float* Wo    = (const float*)d_in[9];
    const float* bo    = (const float*)d_in[10];
    float* out = (float*)d_out;

    float *gq, *gk, *gv, *gx, *gqi, *gki, *gvi, *gwq, *gwk, *gwv, *gwo;
    cudaGetSymbolAddress((void**)&gq,  g_Q);
    cudaGetSymbolAddress((void**)&gk,  g_K);
    cudaGetSymbolAddress((void**)&gv,  g_V);
    cudaGetSymbolAddress((void**)&gx,  g_X);
    cudaGetSymbolAddress((void**)&gqi, g_QI);
    cudaGetSymbolAddress((void**)&gki, g_KI);
    cudaGetSymbolAddress((void**)&gvi, g_VI);
    cudaGetSymbolAddress((void**)&gwq, g_Wq);
    cudaGetSymbolAddress((void**)&gwk, g_Wk);
    cudaGetSymbolAddress((void**)&gwv, g_Wv);
    cudaGetSymbolAddress((void**)&gwo, g_Wo);

    cudaFuncSetAttribute(qkv_gemm_kernel,
                         cudaFuncAttributeMaxDynamicSharedMemorySize,
                         GEMM_SMEM_BYTES);
    cudaFuncSetAttribute(o_gemm_kernel,
                         cudaFuncAttributeMaxDynamicSharedMemorySize,
                         GEMM_SMEM_BYTES);
    cudaFuncSetAttribute(flash_mma_kernel,
                         cudaFuncAttributeMaxDynamicSharedMemorySize,
                         FLASH2_SMEM_BYTES);

    preround_kernel<<<dim3(MTOT * D_ / 1024, 7), 256>>>(
        query, key, value, Wq, Wk, Wv, Wo);

    qkv_gemm_kernel<<<dim3(D_ / 128, MTOT / 128, 3), 256, GEMM_SMEM_BYTES>>>(
        gqi, gki, gvi, gwq, gwk, gwv, bq, bk, bv, gq, gk, gv);

    flash_mma_kernel<<<dim3(L_ / 128, H_, B_), 256, FLASH2_SMEM_BYTES>>>(
        gq, gk, gv, gx);

    o_gemm_kernel<<<dim3(D_ / 128, MTOT / 128), 256, GEMM_SMEM_BYTES>>>(
        gx, gwo, bo, out);
}